// round 14
// baseline (speedup 1.0000x reference)
#include <cuda_runtime.h>
#include <cuda_bf16.h>
#include <cstdint>
#include <cmath>

// Problem dims (fixed for this dataset)
#define B_ROWS 4096
#define N_COLS 8192   // 2B
#define K_DIM  4096
#define INV_T  10.0f  // 1 / TEMP
#define LSE_TH -25.0f // exp(l-m) below this contributes < 1e-10 relative

// GEMM tiling (mma.sync path; tcgen05 unavailable: harness PTX targets sm_103 base)
#define BM 128
#define BN 128
#define BK 64
#define KCHUNKS (K_DIM / BK)            // 64
#define STAGES 3
#define STAGE_BYTES (BM*128 + BN*128)   // 16KB A + 16KB B = 32768
#define SMEM_BYTES (STAGES * STAGE_BYTES)

// ---- scratch (device globals; no runtime allocation allowed) ----
__device__ __nv_bfloat16 g_imb[(size_t)B_ROWS * K_DIM];   // 32 MB
__device__ __nv_bfloat16 g_sb [(size_t)N_COLS * K_DIM];   // 64 MB
__device__ float  g_diag[B_ROWS];
__device__ float  g_rowlse[B_ROWS];
__device__ float  g_collse[B_ROWS];
__device__ float2 g_rowpart[128 * B_ROWS];  // (tileN*2+wn) x row : 4 MB
__device__ float2 g_cpart  [ 64 * B_ROWS];  // (tileM*2+wm) x col : 2 MB

// ---------------- PTX helpers ----------------
__device__ __forceinline__ uint32_t smem_u32(const void* p) {
  uint32_t a;
  asm("{ .reg .u64 t; cvta.to.shared.u64 t, %1; cvt.u32.u64 %0, t; }" : "=r"(a) : "l"(p));
  return a;
}

__device__ __forceinline__ void cp16(uint32_t dst, const void* src) {
  asm volatile("cp.async.cg.shared.global [%0], [%1], 16;" :: "r"(dst), "l"(src));
}

__device__ __forceinline__ void ldmx4(uint32_t (&r)[4], uint32_t addr) {
  asm volatile("ldmatrix.sync.aligned.m8n8.x4.shared.b16 {%0,%1,%2,%3}, [%4];"
               : "=r"(r[0]), "=r"(r[1]), "=r"(r[2]), "=r"(r[3]) : "r"(addr));
}

__device__ __forceinline__ void mma16816(float (&c)[4], const uint32_t (&a)[4],
                                         uint32_t b0, uint32_t b1) {
  asm volatile(
      "mma.sync.aligned.m16n8k16.row.col.f32.bf16.bf16.f32 "
      "{%0,%1,%2,%3}, {%4,%5,%6,%7}, {%8,%9}, {%0,%1,%2,%3};"
      : "+f"(c[0]), "+f"(c[1]), "+f"(c[2]), "+f"(c[3])
      : "r"(a[0]), "r"(a[1]), "r"(a[2]), "r"(a[3]), "r"(b0), "r"(b1));
}

// Thresholded online logsumexp update.
__device__ __forceinline__ void lse_upd(float& m, float& s, float l) {
  if (l > m) {
    s = (m - l > LSE_TH) ? s * __expf(m - l) + 1.f : 1.f;
    m = l;
  } else if (l - m > LSE_TH) {
    s += __expf(l - m);
  }
}

// Merge two (m,s) partials.
__device__ __forceinline__ void lse_merge(float& m, float& s, float m2, float s2) {
  const float mm = fmaxf(m, m2);
  float acc = 0.f;
  if (m  - mm > LSE_TH) acc += s  * __expf(m  - mm);
  if (m2 - mm > LSE_TH) acc += s2 * __expf(m2 - mm);
  m = mm; s = acc;
}

__device__ __forceinline__ void shfl_merge(float& m, float& s, int off) {
  const float om = __shfl_xor_sync(0xFFFFFFFFu, m, off);
  const float os = __shfl_xor_sync(0xFFFFFFFFu, s, off);
  lse_merge(m, s, om, os);
}

// Load one K-chunk (A: 128x64 bf16, B: 128x64 bf16) into SW128-swizzled SMEM.
__device__ __forceinline__ void load_chunk(int tid, uint32_t smA, uint32_t smB,
                                           const __nv_bfloat16* gA,
                                           const __nv_bfloat16* gB) {
  const int row0 = tid >> 3, ch = tid & 7;
  const uint32_t colb = (uint32_t)(ch << 4);
#pragma unroll
  for (int i = 0; i < 8; ++i) {
    const int row = row0 + i * 16;
    uint32_t off = (uint32_t)(row << 7) + colb;
    uint32_t sw = off ^ ((off >> 3) & 0x70u);
    cp16(smA + sw, (const char*)(gA + (size_t)row * K_DIM) + colb);
  }
#pragma unroll
  for (int i = 0; i < 8; ++i) {
    const int row = row0 + i * 16;
    uint32_t off = (uint32_t)(row << 7) + colb;
    uint32_t sw = off ^ ((off >> 3) & 0x70u);
    cp16(smB + sw, (const char*)(gB + (size_t)row * K_DIM) + colb);
  }
  asm volatile("cp.async.commit_group;" ::: "memory");
}

// ---------------- kernels ----------------
// Convert im (16M floats) and s (32M floats) to bf16, vectorized.
__global__ void convert_kernel(const float* __restrict__ im, const float* __restrict__ s) {
  const size_t q_im = (size_t)B_ROWS * K_DIM / 4;
  const size_t q_s  = (size_t)N_COLS * K_DIM / 4;
  const size_t stride = (size_t)gridDim.x * blockDim.x;
  for (size_t i = (size_t)blockIdx.x * blockDim.x + threadIdx.x; i < q_im + q_s; i += stride) {
    if (i < q_im) {
      const float4 v = ((const float4*)im)[i];
      ((__nv_bfloat162*)g_imb)[i * 2 + 0] = __nv_bfloat162(__float2bfloat16(v.x), __float2bfloat16(v.y));
      ((__nv_bfloat162*)g_imb)[i * 2 + 1] = __nv_bfloat162(__float2bfloat16(v.z), __float2bfloat16(v.w));
    } else {
      const size_t j = i - q_im;
      const float4 v = ((const float4*)s)[j];
      ((__nv_bfloat162*)g_sb)[j * 2 + 0] = __nv_bfloat162(__float2bfloat16(v.x), __float2bfloat16(v.y));
      ((__nv_bfloat162*)g_sb)[j * 2 + 1] = __nv_bfloat162(__float2bfloat16(v.z), __float2bfloat16(v.w));
    }
  }
}

// diag[i] = 0.5*(sims_local[i,i] + dot(im_bf16[i], s_bf16[i])). One warp per row.
__global__ void diag_kernel(const float* __restrict__ sims_local) {
  const int row = blockIdx.x * 8 + (threadIdx.x >> 5);
  const int lane = threadIdx.x & 31;
  const __nv_bfloat162* a = (const __nv_bfloat162*)(g_imb + (size_t)row * K_DIM);
  const __nv_bfloat162* b = (const __nv_bfloat162*)(g_sb  + (size_t)row * K_DIM);
  float acc = 0.f;
#pragma unroll 4
  for (int j = lane; j < K_DIM / 2; j += 32) {
    const __nv_bfloat162 av = a[j], bv = b[j];
    acc += __bfloat162float(av.x) * __bfloat162float(bv.x)
         + __bfloat162float(av.y) * __bfloat162float(bv.y);
  }
#pragma unroll
  for (int o = 16; o > 0; o >>= 1) acc += __shfl_xor_sync(0xFFFFFFFFu, acc, o);
  if (lane == 0)
    g_diag[row] = 0.5f * (sims_local[(size_t)row * N_COLS + row] + acc);
}

// Fused GEMM + LSE partials; sim never hits global memory.
// Single launch, grid x = tileN (64), y = tileM (32) (measured-good order).
// tileN < 32: col partials (first half, unmasked). tileN >= 32: masked vs g_diag.
__global__ void __launch_bounds__(128, 2) ntx_gemm_kernel(const float* __restrict__ sims_local) {
  extern __shared__ char smem_raw[];
  const uint32_t sbase = smem_u32(smem_raw);
  const int tid = threadIdx.x;
  const int wid = tid >> 5;
  const int lane = tid & 31;
  const int wm = wid >> 1;        // 0..1 -> M offset wm*64
  const int wn = wid & 1;         // 0..1 -> N offset wn*64
  const int tileN = blockIdx.x;
  const int tileM = blockIdx.y;
  const bool domask = (tileN >= 32);

  const __nv_bfloat16* gA0 = g_imb + (size_t)tileM * BM * K_DIM;
  const __nv_bfloat16* gB0 = g_sb  + (size_t)tileN * BN * K_DIM;

  float c[4][8][4];
#pragma unroll
  for (int mt = 0; mt < 4; ++mt)
#pragma unroll
    for (int nt = 0; nt < 8; ++nt)
#pragma unroll
      for (int e = 0; e < 4; ++e) c[mt][nt][e] = 0.f;

  const int lrow = lane & 15;
  const int lcolb = (lane >> 4) * 16;

  load_chunk(tid, sbase, sbase + BM * 128u, gA0, gB0);
  load_chunk(tid, sbase + STAGE_BYTES, sbase + STAGE_BYTES + BM * 128u, gA0 + BK, gB0 + BK);

  for (int k = 0; k < KCHUNKS; ++k) {
    if (k == KCHUNKS - 1) asm volatile("cp.async.wait_group 0;" ::: "memory");
    else                  asm volatile("cp.async.wait_group 1;" ::: "memory");
    __syncthreads();

    if (k + 2 < KCHUNKS) {
      const uint32_t st = (uint32_t)((k + 2) % STAGES) * STAGE_BYTES;
      load_chunk(tid, sbase + st, sbase + st + BM * 128u,
                 gA0 + (size_t)(k + 2) * BK, gB0 + (size_t)(k + 2) * BK);
    }

    const uint32_t smA = sbase + (uint32_t)(k % STAGES) * STAGE_BYTES;
    const uint32_t smB = smA + BM * 128u;
    const uint32_t aRowOff = ((uint32_t)(wm * 64 + lrow) << 7) + (uint32_t)lcolb;
    const uint32_t bRowOff = ((uint32_t)(wn * 64 + lrow) << 7) + (uint32_t)lcolb;

#pragma unroll
    for (int kk = 0; kk < 4; ++kk) {
      uint32_t a[4][4], b[4][4];
#pragma unroll
      for (int mt = 0; mt < 4; ++mt) {
        const uint32_t off = aRowOff + (uint32_t)(mt * 16 * 128 + kk * 32);
        ldmx4(a[mt], smA + (off ^ ((off >> 3) & 0x70u)));
      }
#pragma unroll
      for (int nb = 0; nb < 4; ++nb) {
        const uint32_t off = bRowOff + (uint32_t)(nb * 16 * 128 + kk * 32);
        ldmx4(b[nb], smB + (off ^ ((off >> 3) & 0x70u)));
      }
#pragma unroll
      for (int mt = 0; mt < 4; ++mt)
#pragma unroll
        for (int nb = 0; nb < 4; ++nb) {
          mma16816(c[mt][nb * 2 + 0], a[mt], b[nb][0], b[nb][2]);
          mma16816(c[mt][nb * 2 + 1], a[mt], b[nb][1], b[nb][3]);
        }
    }
  }

  // ---- epilogue: 0.5*(sims_local+acc) -> in-register LSE partials ----
  const int qr = lane >> 2;        // row within 8
  const int qc = (lane & 3) * 2;   // even col within 8
  const int mbase = tileM * BM + wm * 64;
  const int nbase = tileN * BN + wn * 64;

  float dd[4][2];
  if (domask) {
#pragma unroll
    for (int mt = 0; mt < 4; ++mt)
#pragma unroll
      for (int h = 0; h < 2; ++h)
        dd[mt][h] = g_diag[mbase + mt * 16 + qr + h * 8];
  }

  float rm[4][2], rs[4][2];
#pragma unroll
  for (int mt = 0; mt < 4; ++mt)
#pragma unroll
    for (int h = 0; h < 2; ++h) { rm[mt][h] = -INFINITY; rs[mt][h] = 0.f; }

  // nt-outer: col chains live only 4 regs at a time (avoids spills).
#pragma unroll
  for (int nt = 0; nt < 8; ++nt) {
    const int col = nbase + nt * 8 + qc;
    float cm0 = -INFINITY, cs0 = 0.f, cm1 = -INFINITY, cs1 = 0.f;
#pragma unroll
    for (int mt = 0; mt < 4; ++mt) {
#pragma unroll
      for (int h = 0; h < 2; ++h) {
        const int row = mbase + mt * 16 + qr + h * 8;
        const size_t idx = (size_t)row * N_COLS + col;
        const float2 sl = *(const float2*)(sims_local + idx);
        float vx = 0.5f * (sl.x + c[mt][nt][h * 2 + 0]);
        float vy = 0.5f * (sl.y + c[mt][nt][h * 2 + 1]);
        if (domask) {
          const float d = dd[mt][h];
          if (vx > d) vx = 0.f;
          if (vy > d) vy = 0.f;
        } else {
          lse_upd(cm0, cs0, vx * INV_T);
          lse_upd(cm1, cs1, vy * INV_T);
        }
        lse_upd(rm[mt][h], rs[mt][h], vx * INV_T);
        lse_upd(rm[mt][h], rs[mt][h], vy * INV_T);
      }
    }
    if (!domask) {
      shfl_merge(cm0, cs0, 4);  shfl_merge(cm0, cs0, 8);  shfl_merge(cm0, cs0, 16);
      shfl_merge(cm1, cs1, 4);  shfl_merge(cm1, cs1, 8);  shfl_merge(cm1, cs1, 16);
      if (lane < 4) {
        const int col0 = nbase + nt * 8 + lane * 2;
        g_cpart[(size_t)(tileM * 2 + wm) * B_ROWS + col0 + 0] = make_float2(cm0, cs0);
        g_cpart[(size_t)(tileM * 2 + wm) * B_ROWS + col0 + 1] = make_float2(cm1, cs1);
      }
    }
  }

  // row partials: merge across the 4 lanes of each row quad
#pragma unroll
  for (int mt = 0; mt < 4; ++mt)
#pragma unroll
    for (int h = 0; h < 2; ++h) {
      shfl_merge(rm[mt][h], rs[mt][h], 1);
      shfl_merge(rm[mt][h], rs[mt][h], 2);
      if ((lane & 3) == 0) {
        const int row = mbase + mt * 16 + qr + h * 8;
        g_rowpart[(size_t)(tileN * 2 + wn) * B_ROWS + row] = make_float2(rm[mt][h], rs[mt][h]);
      }
    }
}

// Combine 128 row partials per row -> rowlse.
__global__ void row_combine_kernel() {
  const int row = blockIdx.x * 256 + threadIdx.x;
  float m = -INFINITY;
  for (int i = 0; i < 128; ++i) m = fmaxf(m, g_rowpart[(size_t)i * B_ROWS + row].x);
  float s = 0.f;
  for (int i = 0; i < 128; ++i) {
    const float2 v = g_rowpart[(size_t)i * B_ROWS + row];
    if (v.x - m > LSE_TH) s += v.y * __expf(v.x - m);
  }
  g_rowlse[row] = m + logf(s);
}

// Combine 64 col partials per column -> collse.
__global__ void col_combine_kernel() {
  const int col = blockIdx.x * 256 + threadIdx.x;
  float m = -INFINITY;
  for (int i = 0; i < 64; ++i) m = fmaxf(m, g_cpart[(size_t)i * B_ROWS + col].x);
  float s = 0.f;
  for (int i = 0; i < 64; ++i) {
    const float2 v = g_cpart[(size_t)i * B_ROWS + col];
    if (v.x - m > LSE_TH) s += v.y * __expf(v.x - m);
  }
  g_collse[col] = m + logf(s);
}

__global__ void final_kernel(float* out) {
  double acc = 0.0;
  for (int i = threadIdx.x; i < B_ROWS; i += 256) {
    const double dt = (double)g_diag[i] * (double)INV_T;
    acc += ((double)g_rowlse[i] - dt) + ((double)g_collse[i] - dt);
  }
  __shared__ double sh[256];
  sh[threadIdx.x] = acc;
  __syncthreads();
  for (int o = 128; o > 0; o >>= 1) {
    if (threadIdx.x < o) sh[threadIdx.x] += sh[threadIdx.x + o];
    __syncthreads();
  }
  if (threadIdx.x == 0) out[0] = (float)(sh[0] / (double)B_ROWS);
}

// ---------------- launch ----------------
extern "C" void kernel_launch(void* const* d_in, const int* in_sizes, int n_in,
                              void* d_out, int out_size) {
  (void)in_sizes; (void)n_in; (void)out_size;
  const float* im = (const float*)d_in[0];
  const float* s  = (const float*)d_in[1];
  const float* sl = (const float*)d_in[2];
  float* out = (float*)d_out;

  cudaFuncSetAttribute(ntx_gemm_kernel,
                       cudaFuncAttributeMaxDynamicSharedMemorySize, SMEM_BYTES);

  convert_kernel<<<2048, 256>>>(im, s);
  diag_kernel<<<B_ROWS / 8, 256>>>(sl);
  ntx_gemm_kernel<<<dim3(N_COLS / BN, B_ROWS / BM), 128, SMEM_BYTES>>>(sl);
  row_combine_kernel<<<B_ROWS / 256, 256>>>();
  col_combine_kernel<<<B_ROWS / 256, 256>>>();
  final_kernel<<<1, 256>>>(out);
}

// round 16
// speedup vs baseline: 1.7856x; 1.7856x over previous
#include <cuda_runtime.h>
#include <cuda_bf16.h>
#include <cstdint>
#include <cmath>

// Problem dims (fixed for this dataset)
#define B_ROWS 4096
#define N_COLS 8192   // 2B
#define K_DIM  4096
#define INV_T  10.0f  // 1 / TEMP
#define LSE_TH -25.0f // exp(l-m) below this contributes < 1e-10 relative

// GEMM tiling (mma.sync path; tcgen05 unavailable: harness PTX targets sm_103 base)
#define BM 128
#define BN 128
#define BK 64
#define KCHUNKS (K_DIM / BK)            // 64
#define STAGES 3
#define STAGE_BYTES (BM*128 + BN*128)   // 16KB A + 16KB B = 32768
#define SMEM_BYTES (STAGES * STAGE_BYTES)

#define COL_CHUNKS 128                  // 32 rows per chunk

// ---- scratch (device globals; no runtime allocation allowed) ----
__device__ __nv_bfloat16 g_imb[(size_t)B_ROWS * K_DIM];   // 32 MB
__device__ __nv_bfloat16 g_sb [(size_t)N_COLS * K_DIM];   // 64 MB
__device__ float  g_sim[(size_t)B_ROWS * N_COLS];         // 128 MB
__device__ float  g_diag[B_ROWS];
__device__ float  g_rowlse[B_ROWS];
__device__ float  g_collse[B_ROWS];
__device__ float2 g_colpart[COL_CHUNKS * B_ROWS];         // 4 MB

// ---------------- PTX helpers ----------------
__device__ __forceinline__ uint32_t smem_u32(const void* p) {
  uint32_t a;
  asm("{ .reg .u64 t; cvta.to.shared.u64 t, %1; cvt.u32.u64 %0, t; }" : "=r"(a) : "l"(p));
  return a;
}

__device__ __forceinline__ void cp16(uint32_t dst, const void* src) {
  asm volatile("cp.async.cg.shared.global [%0], [%1], 16;" :: "r"(dst), "l"(src));
}

__device__ __forceinline__ void ldmx4(uint32_t (&r)[4], uint32_t addr) {
  asm volatile("ldmatrix.sync.aligned.m8n8.x4.shared.b16 {%0,%1,%2,%3}, [%4];"
               : "=r"(r[0]), "=r"(r[1]), "=r"(r[2]), "=r"(r[3]) : "r"(addr));
}

__device__ __forceinline__ void mma16816(float (&c)[4], const uint32_t (&a)[4],
                                         uint32_t b0, uint32_t b1) {
  asm volatile(
      "mma.sync.aligned.m16n8k16.row.col.f32.bf16.bf16.f32 "
      "{%0,%1,%2,%3}, {%4,%5,%6,%7}, {%8,%9}, {%0,%1,%2,%3};"
      : "+f"(c[0]), "+f"(c[1]), "+f"(c[2]), "+f"(c[3])
      : "r"(a[0]), "r"(a[1]), "r"(a[2]), "r"(a[3]), "r"(b0), "r"(b1));
}

// Thresholded online logsumexp update.
__device__ __forceinline__ void lse_upd(float& m, float& s, float l) {
  if (l > m) {
    s = (m - l > LSE_TH) ? s * __expf(m - l) + 1.f : 1.f;
    m = l;
  } else if (l - m > LSE_TH) {
    s += __expf(l - m);
  }
}

// Merge two (m,s) partials.
__device__ __forceinline__ void lse_merge(float& m, float& s, float m2, float s2) {
  const float mm = fmaxf(m, m2);
  float acc = 0.f;
  if (m  - mm > LSE_TH) acc += s  * __expf(m  - mm);
  if (m2 - mm > LSE_TH) acc += s2 * __expf(m2 - mm);
  m = mm; s = acc;
}

// Load one K-chunk (A: 128x64 bf16, B: 128x64 bf16) into SW128-swizzled SMEM.
__device__ __forceinline__ void load_chunk(int tid, uint32_t smA, uint32_t smB,
                                           const __nv_bfloat16* gA,
                                           const __nv_bfloat16* gB) {
  const int row0 = tid >> 3, ch = tid & 7;       // row0 0..15
  const uint32_t colb = (uint32_t)(ch << 4);
#pragma unroll
  for (int i = 0; i < 8; ++i) {
    const int row = row0 + i * 16;
    uint32_t off = (uint32_t)(row << 7) + colb;
    uint32_t sw = off ^ ((off >> 3) & 0x70u);
    cp16(smA + sw, (const char*)(gA + (size_t)row * K_DIM) + colb);
  }
#pragma unroll
  for (int i = 0; i < 8; ++i) {
    const int row = row0 + i * 16;
    uint32_t off = (uint32_t)(row << 7) + colb;
    uint32_t sw = off ^ ((off >> 3) & 0x70u);
    cp16(smB + sw, (const char*)(gB + (size_t)row * K_DIM) + colb);
  }
  asm volatile("cp.async.commit_group;" ::: "memory");
}

// Load A/B ldmatrix fragments for one kk step.
__device__ __forceinline__ void load_frags(uint32_t smA, uint32_t smB,
                                           uint32_t aRowOff, uint32_t bRowOff, int kk,
                                           uint32_t (&a)[4][4], uint32_t (&b)[4][4]) {
#pragma unroll
  for (int mt = 0; mt < 4; ++mt) {
    const uint32_t off = aRowOff + (uint32_t)(mt * 16 * 128 + kk * 32);
    ldmx4(a[mt], smA + (off ^ ((off >> 3) & 0x70u)));
  }
#pragma unroll
  for (int nb = 0; nb < 4; ++nb) {
    const uint32_t off = bRowOff + (uint32_t)(nb * 16 * 128 + kk * 32);
    ldmx4(b[nb], smB + (off ^ ((off >> 3) & 0x70u)));
  }
}

// ---------------- kernels ----------------
// Convert im (16M floats) and s (32M floats) to bf16, vectorized float4 -> bf16x2 pairs.
__global__ void convert_kernel(const float* __restrict__ im, const float* __restrict__ s) {
  const size_t q_im = (size_t)B_ROWS * K_DIM / 4;
  const size_t q_s  = (size_t)N_COLS * K_DIM / 4;
  const size_t stride = (size_t)gridDim.x * blockDim.x;
  for (size_t i = (size_t)blockIdx.x * blockDim.x + threadIdx.x; i < q_im + q_s; i += stride) {
    if (i < q_im) {
      const float4 v = ((const float4*)im)[i];
      ((__nv_bfloat162*)g_imb)[i * 2 + 0] = __nv_bfloat162(__float2bfloat16(v.x), __float2bfloat16(v.y));
      ((__nv_bfloat162*)g_imb)[i * 2 + 1] = __nv_bfloat162(__float2bfloat16(v.z), __float2bfloat16(v.w));
    } else {
      const size_t j = i - q_im;
      const float4 v = ((const float4*)s)[j];
      ((__nv_bfloat162*)g_sb)[j * 2 + 0] = __nv_bfloat162(__float2bfloat16(v.x), __float2bfloat16(v.y));
      ((__nv_bfloat162*)g_sb)[j * 2 + 1] = __nv_bfloat162(__float2bfloat16(v.z), __float2bfloat16(v.w));
    }
  }
}

// sim = 0.5*sims_local + 0.5*(im @ s.T) -> g_sim (fp32); diag fused.
// 128 threads, 4 warps in 2x2 grid of 64x64 warp tiles.
// Grid order (measured-good): x = tileN (64), y = tileM (32).
// kk-pipelined mainloop: double-buffered fragments overlap LDSM with MMA.
__global__ void __launch_bounds__(128, 2) ntx_gemm_kernel(const float* __restrict__ sims_local) {
  extern __shared__ char smem_raw[];
  const uint32_t sbase = smem_u32(smem_raw);
  const int tid = threadIdx.x;
  const int wid = tid >> 5;
  const int lane = tid & 31;
  const int wm = wid >> 1;        // 0..1 -> M offset wm*64
  const int wn = wid & 1;         // 0..1 -> N offset wn*64
  const int tileN = blockIdx.x;
  const int tileM = blockIdx.y;

  const __nv_bfloat16* gA0 = g_imb + (size_t)tileM * BM * K_DIM;
  const __nv_bfloat16* gB0 = g_sb  + (size_t)tileN * BN * K_DIM;

  float c[4][8][4];
#pragma unroll
  for (int mt = 0; mt < 4; ++mt)
#pragma unroll
    for (int nt = 0; nt < 8; ++nt)
#pragma unroll
      for (int e = 0; e < 4; ++e) c[mt][nt][e] = 0.f;

  const int lrow = lane & 15;           // row within 16-row tile
  const int lcolb = (lane >> 4) * 16;   // 0 or 16 bytes (k-half)

  // prologue: STAGES-1 chunks in flight
  load_chunk(tid, sbase, sbase + BM * 128u, gA0, gB0);
  load_chunk(tid, sbase + STAGE_BYTES, sbase + STAGE_BYTES + BM * 128u, gA0 + BK, gB0 + BK);

  for (int k = 0; k < KCHUNKS; ++k) {
    if (k == KCHUNKS - 1) asm volatile("cp.async.wait_group 0;" ::: "memory");
    else                  asm volatile("cp.async.wait_group 1;" ::: "memory");
    __syncthreads();

    if (k + 2 < KCHUNKS) {
      const uint32_t st = (uint32_t)((k + 2) % STAGES) * STAGE_BYTES;
      load_chunk(tid, sbase + st, sbase + st + BM * 128u,
                 gA0 + (size_t)(k + 2) * BK, gB0 + (size_t)(k + 2) * BK);
    }

    const uint32_t smA = sbase + (uint32_t)(k % STAGES) * STAGE_BYTES;
    const uint32_t smB = smA + BM * 128u;
    const uint32_t aRowOff = ((uint32_t)(wm * 64 + lrow) << 7) + (uint32_t)lcolb;
    const uint32_t bRowOff = ((uint32_t)(wn * 64 + lrow) << 7) + (uint32_t)lcolb;

    uint32_t afr[2][4][4], bfr[2][4][4];
    load_frags(smA, smB, aRowOff, bRowOff, 0, afr[0], bfr[0]);
#pragma unroll
    for (int kk = 0; kk < 4; ++kk) {
      const int cur = kk & 1;
      if (kk < 3)
        load_frags(smA, smB, aRowOff, bRowOff, kk + 1, afr[cur ^ 1], bfr[cur ^ 1]);
#pragma unroll
      for (int mt = 0; mt < 4; ++mt)
#pragma unroll
        for (int nb = 0; nb < 4; ++nb) {
          mma16816(c[mt][nb * 2 + 0], afr[cur][mt], bfr[cur][nb][0], bfr[cur][nb][2]);
          mma16816(c[mt][nb * 2 + 1], afr[cur][mt], bfr[cur][nb][1], bfr[cur][nb][3]);
        }
    }
  }

  // epilogue: fused 0.5*(sims_local + acc), float2 stores, inline diag
  const int qr = lane >> 2;        // 0..7 row within 8
  const int qc = (lane & 3) * 2;   // even col within 8
  const int mbase = tileM * BM + wm * 64;
  const int nbase = tileN * BN + wn * 64;
#pragma unroll
  for (int mt = 0; mt < 4; ++mt) {
#pragma unroll
    for (int nt = 0; nt < 8; ++nt) {
      const int col = nbase + nt * 8 + qc;
#pragma unroll
      for (int h = 0; h < 2; ++h) {
        const int row = mbase + mt * 16 + qr + h * 8;
        const size_t idx = (size_t)row * N_COLS + col;
        const float2 sl = *(const float2*)(sims_local + idx);
        const float vx = 0.5f * (sl.x + c[mt][nt][h * 2 + 0]);
        const float vy = 0.5f * (sl.y + c[mt][nt][h * 2 + 1]);
        *(float2*)(g_sim + idx) = make_float2(vx, vy);
        if (row == col)     g_diag[row] = vx;
        if (row == col + 1) g_diag[row] = vy;
      }
    }
  }
}

// Row LSE with masking (second-half columns zeroed when > diag).
// 4 independent online chains + exp-threshold; fully unrolled loop for MLP.
__global__ void row_lse_kernel() {
  const int row = blockIdx.x;
  const float d = g_diag[row];
  const float4* p = (const float4*)(g_sim + (size_t)row * N_COLS);
  float m0 = -INFINITY, s0 = 0.f, m1 = -INFINITY, s1 = 0.f;
  float m2 = -INFINITY, s2 = 0.f, m3 = -INFINITY, s3 = 0.f;
#pragma unroll
  for (int it = 0; it < N_COLS / 4 / 256; ++it) {
    const int j4 = it * 256 + threadIdx.x;
    float4 v = p[j4];
    if (j4 * 4 >= B_ROWS) {   // second half: mask entries above diagonal
      if (v.x > d) v.x = 0.f;
      if (v.y > d) v.y = 0.f;
      if (v.z > d) v.z = 0.f;
      if (v.w > d) v.w = 0.f;
    }
    lse_upd(m0, s0, v.x * INV_T);
    lse_upd(m1, s1, v.y * INV_T);
    lse_upd(m2, s2, v.z * INV_T);
    lse_upd(m3, s3, v.w * INV_T);
  }
  lse_merge(m0, s0, m1, s1);
  lse_merge(m2, s2, m3, s3);
  lse_merge(m0, s0, m2, s2);

  __shared__ float sm[256], ss[256];
  sm[threadIdx.x] = m0; ss[threadIdx.x] = s0;
  __syncthreads();
  for (int o = 128; o > 0; o >>= 1) {
    if (threadIdx.x < o) {
      float mm = sm[threadIdx.x], scur = ss[threadIdx.x];
      lse_merge(mm, scur, sm[threadIdx.x + o], ss[threadIdx.x + o]);
      sm[threadIdx.x] = mm; ss[threadIdx.x] = scur;
    }
    __syncthreads();
  }
  if (threadIdx.x == 0) g_rowlse[row] = sm[0] + logf(ss[0]);
}

// Column LSE partials over 32-row chunks; 4 columns per thread via float4.
// grid = (B_ROWS/1024, COL_CHUNKS) = (4, 128) = 512 blocks. Unrolled x4 (MLP>=4).
__global__ void col_part_kernel() {
  const int col = (blockIdx.x * 256 + threadIdx.x) * 4;
  const int rc = blockIdx.y;  // 0..127
  const float* p = g_sim + (size_t)(rc * 32) * N_COLS + col;
  float4 m = make_float4(-INFINITY, -INFINITY, -INFINITY, -INFINITY);
  float4 s = make_float4(0.f, 0.f, 0.f, 0.f);
#pragma unroll 1
  for (int r0 = 0; r0 < 32; r0 += 4) {
    float4 v[4];
#pragma unroll
    for (int u = 0; u < 4; ++u)
      v[u] = *(const float4*)(p + (size_t)(r0 + u) * N_COLS);
#pragma unroll
    for (int u = 0; u < 4; ++u) {
      lse_upd(m.x, s.x, v[u].x * INV_T);
      lse_upd(m.y, s.y, v[u].y * INV_T);
      lse_upd(m.z, s.z, v[u].z * INV_T);
      lse_upd(m.w, s.w, v[u].w * INV_T);
    }
  }
  g_colpart[rc * B_ROWS + col + 0] = make_float2(m.x, s.x);
  g_colpart[rc * B_ROWS + col + 1] = make_float2(m.y, s.y);
  g_colpart[rc * B_ROWS + col + 2] = make_float2(m.z, s.z);
  g_colpart[rc * B_ROWS + col + 3] = make_float2(m.w, s.w);
}

__global__ void col_combine_kernel() {
  const int col = blockIdx.x * 256 + threadIdx.x;
  float m = -INFINITY;
  for (int rc = 0; rc < COL_CHUNKS; ++rc) m = fmaxf(m, g_colpart[rc * B_ROWS + col].x);
  float s = 0.f;
  for (int rc = 0; rc < COL_CHUNKS; ++rc) {
    const float2 v = g_colpart[rc * B_ROWS + col];
    if (v.x - m > LSE_TH) s += v.y * __expf(v.x - m);
  }
  g_collse[col] = m + logf(s);
}

__global__ void final_kernel(float* out) {
  double acc = 0.0;
  for (int i = threadIdx.x; i < B_ROWS; i += 256) {
    const double dt = (double)g_diag[i] * (double)INV_T;
    acc += ((double)g_rowlse[i] - dt) + ((double)g_collse[i] - dt);
  }
  __shared__ double sh[256];
  sh[threadIdx.x] = acc;
  __syncthreads();
  for (int o = 128; o > 0; o >>= 1) {
    if (threadIdx.x < o) sh[threadIdx.x] += sh[threadIdx.x + o];
    __syncthreads();
  }
  if (threadIdx.x == 0) out[0] = (float)(sh[0] / (double)B_ROWS);
}

// ---------------- launch ----------------
extern "C" void kernel_launch(void* const* d_in, const int* in_sizes, int n_in,
                              void* d_out, int out_size) {
  (void)in_sizes; (void)n_in; (void)out_size;
  const float* im = (const float*)d_in[0];
  const float* s  = (const float*)d_in[1];
  const float* sl = (const float*)d_in[2];
  float* out = (float*)d_out;

  cudaFuncSetAttribute(ntx_gemm_kernel,
                       cudaFuncAttributeMaxDynamicSharedMemorySize, SMEM_BYTES);

  convert_kernel<<<2048, 256>>>(im, s);
  ntx_gemm_kernel<<<dim3(N_COLS / BN, B_ROWS / BM), 128, SMEM_BYTES>>>(sl);
  row_lse_kernel<<<B_ROWS, 256>>>();
  col_part_kernel<<<dim3(B_ROWS / 1024, COL_CHUNKS), 256>>>();
  col_combine_kernel<<<B_ROWS / 256, 256>>>();
  final_kernel<<<1, 256>>>(out);
}